// round 2
// baseline (speedup 1.0000x reference)
#include <cuda_runtime.h>
#include <cstdint>

// PPRGo: out[n,:] = sum_k ( mask(wei[n,k]) / (sum_k mask + 1e-12) ) * emb_table[nei[n,k], :]
// N=200000, TOPK=32, EMB=64.
// NOTE: nei is int32 on the wire (JAX x64 disabled downcasts jnp.int64 -> int32).
// One warp per node. Lane k owns neighbor k for the weight/index phase;
// for the gather phase each lane owns 2 embedding components (float2).

static constexpr int TOPK = 32;
static constexpr int EMB  = 64;

__global__ __launch_bounds__(256)
void pprgo_kernel(const float* __restrict__ emb,   // [N, 64]
                  const float* __restrict__ wei,   // [N, 32]
                  const int*   __restrict__ nei,   // [N, 32] int32
                  float* __restrict__ out,         // [N, 64]
                  int n_nodes)
{
    const int warp_id = (blockIdx.x * blockDim.x + threadIdx.x) >> 5;
    const int lane    = threadIdx.x & 31;
    if (warp_id >= n_nodes) return;

    const size_t row = (size_t)warp_id * TOPK;

    // --- weight phase: lane k handles neighbor k ---
    float w  = wei[row + lane];
    float m  = (w != 0.0f) ? 1.0f : 0.0f;
    float s  = m;
    #pragma unroll
    for (int o = 16; o > 0; o >>= 1)
        s += __shfl_xor_sync(0xFFFFFFFFu, s, o);
    const float myw = m * (1.0f / (s + 1e-12f));

    const int myidx = nei[row + lane];

    // --- gather phase: lane owns float2 slice [2*lane, 2*lane+1] of EMB ---
    const float2* __restrict__ e2 = reinterpret_cast<const float2*>(emb);

    float accx = 0.0f, accy = 0.0f;

    #pragma unroll
    for (int k = 0; k < TOPK; k += 8) {
        int i0 = __shfl_sync(0xFFFFFFFFu, myidx, k + 0);
        int i1 = __shfl_sync(0xFFFFFFFFu, myidx, k + 1);
        int i2 = __shfl_sync(0xFFFFFFFFu, myidx, k + 2);
        int i3 = __shfl_sync(0xFFFFFFFFu, myidx, k + 3);
        int i4 = __shfl_sync(0xFFFFFFFFu, myidx, k + 4);
        int i5 = __shfl_sync(0xFFFFFFFFu, myidx, k + 5);
        int i6 = __shfl_sync(0xFFFFFFFFu, myidx, k + 6);
        int i7 = __shfl_sync(0xFFFFFFFFu, myidx, k + 7);

        float w0 = __shfl_sync(0xFFFFFFFFu, myw, k + 0);
        float w1 = __shfl_sync(0xFFFFFFFFu, myw, k + 1);
        float w2 = __shfl_sync(0xFFFFFFFFu, myw, k + 2);
        float w3 = __shfl_sync(0xFFFFFFFFu, myw, k + 3);
        float w4 = __shfl_sync(0xFFFFFFFFu, myw, k + 4);
        float w5 = __shfl_sync(0xFFFFFFFFu, myw, k + 5);
        float w6 = __shfl_sync(0xFFFFFFFFu, myw, k + 6);
        float w7 = __shfl_sync(0xFFFFFFFFu, myw, k + 7);

        // 8 independent loads in flight (MLP=8 per warp)
        float2 v0 = e2[(size_t)i0 * (EMB/2) + lane];
        float2 v1 = e2[(size_t)i1 * (EMB/2) + lane];
        float2 v2 = e2[(size_t)i2 * (EMB/2) + lane];
        float2 v3 = e2[(size_t)i3 * (EMB/2) + lane];
        float2 v4 = e2[(size_t)i4 * (EMB/2) + lane];
        float2 v5 = e2[(size_t)i5 * (EMB/2) + lane];
        float2 v6 = e2[(size_t)i6 * (EMB/2) + lane];
        float2 v7 = e2[(size_t)i7 * (EMB/2) + lane];

        accx += w0 * v0.x; accy += w0 * v0.y;
        accx += w1 * v1.x; accy += w1 * v1.y;
        accx += w2 * v2.x; accy += w2 * v2.y;
        accx += w3 * v3.x; accy += w3 * v3.y;
        accx += w4 * v4.x; accy += w4 * v4.y;
        accx += w5 * v5.x; accy += w5 * v5.y;
        accx += w6 * v6.x; accy += w6 * v6.y;
        accx += w7 * v7.x; accy += w7 * v7.y;
    }

    float2* __restrict__ o2 = reinterpret_cast<float2*>(out);
    o2[(size_t)warp_id * (EMB/2) + lane] = make_float2(accx, accy);
}

extern "C" void kernel_launch(void* const* d_in, const int* in_sizes, int n_in,
                              void* d_out, int out_size)
{
    const float* emb = (const float*)d_in[0];   // [N, 64]
    const float* wei = (const float*)d_in[1];   // [N, 32]
    const int*   nei = (const int*)d_in[2];     // [N, 32] int32
    float*       out = (float*)d_out;           // [N, 1, 64]

    const int n_nodes = in_sizes[1] / TOPK;     // 200000

    const int threads = 256;                    // 8 warps/block
    const int warps_per_block = threads / 32;
    const int blocks = (n_nodes + warps_per_block - 1) / warps_per_block;

    pprgo_kernel<<<blocks, threads>>>(emb, wei, nei, out, n_nodes);
}